// round 16
// baseline (speedup 1.0000x reference)
#include <cuda_runtime.h>
#include <cuda_fp16.h>
#include <mma.h>
#include <math.h>

using namespace nvcuda;

#define Nn 100000
#define Ee 1600000
#define NSB 196   // ceil(Nn/512)
#define NPAD (Nn + 64)   // tables padded so tail WMMA tiles read zeroed .bss

typedef unsigned long long ull;

// ---------------- scratch (device globals) -----------------------------------
__device__ int   g_rowptr[Nn + 1];
__device__ int   g_cursor[Nn];
__device__ int   g_colidx[Ee];
__device__ int   g_bsum[NSB];
__device__ int   g_is64;
__device__ float g_out [(size_t)Nn * 64];
__device__ __align__(16) __half2 g_x16[(size_t)NPAD * 32];  // fp16 x rows
__device__ __align__(16) __half2 g_h16[(size_t)NPAD * 32];  // fp16 h rows
__device__ __align__(16) __half  g_z16[(size_t)Nn * 16];    // layer-3 z rows (fp16)
__device__ float g_bnsum[2][64];
__device__ float g_bnsq [2][64];

__device__ __forceinline__ int edge_at(const void* ei, long long i, int is64) {
    return is64 ? (int)__ldg(&((const long long*)ei)[i]) : __ldg(&((const int*)ei)[i]);
}

// ---------------- init: cursor zero + BN zero + dtype detect + x->fp16 -------
__global__ void k_init(const void* ei, const float* __restrict__ x) {
    int i = blockIdx.x * blockDim.x + threadIdx.x;
    if (i < Nn) g_cursor[i] = 0;
    if (blockIdx.x == 0) {
        if (threadIdx.x < 64) {
            g_bnsum[0][threadIdx.x] = 0.f; g_bnsq[0][threadIdx.x] = 0.f;
            g_bnsum[1][threadIdx.x] = 0.f; g_bnsq[1][threadIdx.x] = 0.f;
        }
        if (threadIdx.x >= 64 && threadIdx.x < 96) {
            int lane = threadIdx.x - 64;
            const long long* q = (const long long*)ei;
            long long v = q[(long long)lane * 33331];
            unsigned bad = __ballot_sync(0xffffffffu, v < 0 || v >= Nn);
            if (lane == 0) g_is64 = (bad == 0) ? 1 : 0;
        }
    }
    long long stride = (long long)gridDim.x * blockDim.x;
    const float2* p = (const float2*)x;
    for (long long t = i; t < (long long)Nn * 32; t += stride)
        g_x16[t] = __float22half2_rn(__ldg(p + t));
}

// ---------------- CSR build --------------------------------------------------
__global__ void k_hist(const void* ei) {
    int is64 = g_is64;
    long long stride = (long long)gridDim.x * blockDim.x;
    for (long long e = blockIdx.x * (long long)blockDim.x + threadIdx.x; e < Ee; e += stride) {
        int d = edge_at(ei, Ee + e, is64);
        atomicAdd(&g_cursor[d], 1);
    }
}

__global__ void k_scan1() {
    __shared__ int sh[512];
    int i = blockIdx.x * 512 + threadIdx.x;
    int v = (i < Nn) ? g_cursor[i] : 0;
    sh[threadIdx.x] = v;
    __syncthreads();
    for (int off = 1; off < 512; off <<= 1) {
        int t = (threadIdx.x >= off) ? sh[threadIdx.x - off] : 0;
        __syncthreads();
        sh[threadIdx.x] += t;
        __syncthreads();
    }
    if (i < Nn) g_rowptr[i + 1] = sh[threadIdx.x];
    if (threadIdx.x == 511) g_bsum[blockIdx.x] = sh[511];
}

__global__ void k_scan2b() {
    __shared__ int sh[256];
    int tid = threadIdx.x;
    int v = (tid < NSB) ? g_bsum[tid] : 0;
    sh[tid] = v;
    __syncthreads();
    for (int off = 1; off < 256; off <<= 1) {
        int t = (tid >= off) ? sh[tid - off] : 0;
        __syncthreads();
        sh[tid] += t;
        __syncthreads();
    }
    if (tid < NSB) g_bsum[tid] = sh[tid] - v;   // exclusive
}

__global__ void k_scan3() {
    int i = blockIdx.x * blockDim.x + threadIdx.x;
    if (i < Nn) {
        int fin = g_rowptr[i + 1] + g_bsum[i >> 9];
        g_rowptr[i + 1] = fin;
        if (i + 1 < Nn) g_cursor[i + 1] = fin;
    }
    if (i == 0) { g_rowptr[0] = 0; g_cursor[0] = 0; }
}

__global__ void k_scatter(const void* ei) {
    int is64 = g_is64;
    long long stride = (long long)gridDim.x * blockDim.x;
    for (long long e = blockIdx.x * (long long)blockDim.x + threadIdx.x; e < Ee; e += stride) {
        int d = edge_at(ei, Ee + e, is64);
        int s = edge_at(ei, e,      is64);
        int pos = atomicAdd(&g_cursor[d], 1);
        g_colidx[pos] = s;
    }
}

// ---------------- FUSED agg + WMMA dual-GEMM + bias + L2 norm + BN-stats -----
// Phase A: 8 warps compute the block's 64 mean rows into smem (fp16).
// Phase B: WMMA out[r] = mean[r]@Wl^T + own16[r]@Wr^T + b ; L2-norm -> g_out.
// Phase C: R15-proven epilogue with fused BN column stats.
__global__ void __launch_bounds__(256) k_aggemm(int which,
                                                const float* __restrict__ Wl,
                                                const float* __restrict__ Wr,
                                                const float* __restrict__ b) {
    __shared__ __align__(16) __half sWl[4096];
    __shared__ __align__(16) __half sWr[4096];
    __shared__ __align__(16) __half sM[64 * 64];   // mean tile (fp16)
    __shared__ __align__(16) float sC[64 * 68];
    __shared__ float sb[64];
    __shared__ float sSum[64], sSq[64];

    const int T = threadIdx.x;
    const int row0 = blockIdx.x * 64;
    const int warp = T >> 5, lane = T & 31;

    for (int i = T; i < 4096; i += 256) {
        sWl[i] = __float2half_rn(Wl[i]);
        sWr[i] = __float2half_rn(Wr[i]);
    }
    if (T < 64) { sb[T] = b[T]; sSum[T] = 0.f; sSq[T] = 0.f; }

    // ---- Phase A: gather means (warp per node, 8 nodes per warp) ----
    {
        const __half2* __restrict__ p = which ? g_h16 : g_x16;
        __half2* sM2 = (__half2*)sM;
        #pragma unroll 1
        for (int i = warp; i < 64; i += 8) {
            int w = row0 + i;
            float ax = 0.f, ay = 0.f;
            if (w < Nn) {
                int beg = g_rowptr[w], end = g_rowptr[w + 1];
                for (int e = beg; e < end; e += 32) {
                    int cnt = min(32, end - e);
                    int s = (lane < cnt) ? __ldg(&g_colidx[e + lane]) : 0;
                    int j = 0;
                    for (; j + 4 <= cnt; j += 4) {
                        int s0 = __shfl_sync(0xffffffffu, s, j);
                        int s1 = __shfl_sync(0xffffffffu, s, j + 1);
                        int s2 = __shfl_sync(0xffffffffu, s, j + 2);
                        int s3 = __shfl_sync(0xffffffffu, s, j + 3);
                        float2 v0 = __half22float2(__ldg(p + (size_t)s0 * 32 + lane));
                        float2 v1 = __half22float2(__ldg(p + (size_t)s1 * 32 + lane));
                        float2 v2 = __half22float2(__ldg(p + (size_t)s2 * 32 + lane));
                        float2 v3 = __half22float2(__ldg(p + (size_t)s3 * 32 + lane));
                        ax += v0.x + v1.x + v2.x + v3.x;
                        ay += v0.y + v1.y + v2.y + v3.y;
                    }
                    for (; j < cnt; j++) {
                        int sj = __shfl_sync(0xffffffffu, s, j);
                        float2 v = __half22float2(__ldg(p + (size_t)sj * 32 + lane));
                        ax += v.x; ay += v.y;
                    }
                }
                float inv = 1.0f / (float)max(end - beg, 1);
                ax *= inv; ay *= inv;
            }
            sM2[i * 32 + lane] = __floats2half2_rn(ax, ay);
        }
    }
    __syncthreads();

    // ---- Phase B: WMMA ----
    const __half* __restrict__ own = (const __half*)(which ? g_h16 : g_x16);
    #pragma unroll
    for (int t = warp; t < 16; t += 8) {
        int tr = t >> 2, tc = t & 3;
        wmma::fragment<wmma::accumulator, 16, 16, 16, float> acc;
        wmma::fill_fragment(acc, 0.0f);
        const __half* Ar = sM + tr * 16 * 64;
        const __half* Hr = own + (size_t)(row0 + tr * 16) * 64;
        #pragma unroll
        for (int ks = 0; ks < 4; ks++) {
            wmma::fragment<wmma::matrix_a, 16, 16, 16, __half, wmma::row_major> a;
            wmma::fragment<wmma::matrix_b, 16, 16, 16, __half, wmma::col_major> w;
            wmma::load_matrix_sync(a, Ar + ks * 16, 64);
            wmma::load_matrix_sync(w, sWl + ks * 16 + tc * 16 * 64, 64);
            wmma::mma_sync(acc, a, w, acc);
            wmma::load_matrix_sync(a, Hr + ks * 16, 64);
            wmma::load_matrix_sync(w, sWr + ks * 16 + tc * 16 * 64, 64);
            wmma::mma_sync(acc, a, w, acc);
        }
        wmma::store_matrix_sync(sC + tr * 16 * 68 + tc * 16, acc, 68, wmma::mem_row_major);
    }
    __syncthreads();

    // ---- Phase C: bias + L2 norm + store fp32 + fused BN stats (R15) ----
    int row = T >> 2, seg = T & 3;
    const float* crow = sC + row * 68 + seg * 16;
    float v[16];
    float s = 0.f;
    #pragma unroll
    for (int i = 0; i < 16; i++) {
        float t = crow[i] + sb[seg * 16 + i];
        v[i] = t;
        s += t * t;
    }
    s += __shfl_xor_sync(0xffffffffu, s, 1);
    s += __shfl_xor_sync(0xffffffffu, s, 2);
    float sc = 1.0f / fmaxf(sqrtf(s), 1e-12f);
    int grow = row0 + row;
    bool live = (grow < Nn);
    if (live) {
        float4* o = (float4*)(g_out + (size_t)grow * 64 + seg * 16);
        #pragma unroll
        for (int j4 = 0; j4 < 4; j4++)
            o[j4] = make_float4(v[j4 * 4] * sc, v[j4 * 4 + 1] * sc,
                                v[j4 * 4 + 2] * sc, v[j4 * 4 + 3] * sc);
    }
    #pragma unroll
    for (int half = 0; half < 2; half++) {
        float sv[8], qv[8];
        #pragma unroll
        for (int i = 0; i < 8; i++) {
            float t = live ? v[half * 8 + i] * sc : 0.f;
            sv[i] = t; qv[i] = t * t;
        }
        #pragma unroll
        for (int off = 4; off <= 16; off <<= 1) {
            #pragma unroll
            for (int i = 0; i < 8; i++) {
                sv[i] += __shfl_xor_sync(0xffffffffu, sv[i], off);
                qv[i] += __shfl_xor_sync(0xffffffffu, qv[i], off);
            }
        }
        if ((lane >> 2) == 0) {
            #pragma unroll
            for (int i = 0; i < 8; i++) {
                int col = seg * 16 + half * 8 + i;
                atomicAdd(&sSum[col], sv[i]);
                atomicAdd(&sSq[col],  qv[i]);
            }
        }
    }
    __syncthreads();
    if (T < 64) {
        atomicAdd(&g_bnsum[which][T], sSum[T]);
        atomicAdd(&g_bnsq [which][T], sSq[T]);
    }
}

// ---------------- bn apply (+ReLU) -> fp16 g_h16 (layer-1 only) --------------
__global__ void k_bnapply(int slot, const float* __restrict__ gamma,
                          const float* __restrict__ beta) {
    __shared__ float ssc[64], ssh[64];
    if (threadIdx.x < 64) {
        int j = threadIdx.x;
        float mu  = g_bnsum[slot][j] * (1.0f / Nn);
        float var = g_bnsq[slot][j] * (1.0f / Nn) - mu * mu;
        float sc  = rsqrtf(var + 1e-5f) * gamma[j];
        ssc[j] = sc;
        ssh[j] = beta[j] - mu * sc;
    }
    __syncthreads();
    long long stride = (long long)gridDim.x * blockDim.x;
    const float2* p = (const float2*)g_out;
    for (long long i = blockIdx.x * (long long)blockDim.x + threadIdx.x;
         i < (long long)Nn * 32; i += stride) {
        int c2 = (int)(i & 31);
        float2 v = p[i];
        float y0 = fmaxf(v.x * ssc[c2 * 2]     + ssh[c2 * 2],     0.f);
        float y1 = fmaxf(v.y * ssc[c2 * 2 + 1] + ssh[c2 * 2 + 1], 0.f);
        g_h16[i] = __floats2half2_rn(y0, y1);
    }
}

// ---------------- FUSED BN(1)+ReLU + layer-3 projection ----------------------
// thread per row: h = relu(bn(g_out[r])); z16[r] = h@Wl3^T; out[r] = h@Wr3^T+b3
__global__ void __launch_bounds__(256) k_bnproj(const float* __restrict__ gamma,
                                                const float* __restrict__ beta,
                                                const float* __restrict__ Wl,
                                                const float* __restrict__ Wr,
                                                const float* __restrict__ b,
                                                float* __restrict__ out) {
    __shared__ float sWl[640];
    __shared__ float sWr[640];
    __shared__ float sb[10];
    __shared__ float ssc[64], ssh[64];
    for (int i = threadIdx.x; i < 640; i += 256) {
        int j = i / 64, k = i % 64;
        sWl[k * 10 + j] = Wl[i];
        sWr[k * 10 + j] = Wr[i];
    }
    if (threadIdx.x < 10) sb[threadIdx.x] = b[threadIdx.x];
    if (threadIdx.x >= 64 && threadIdx.x < 128) {
        int j = threadIdx.x - 64;
        float mu  = g_bnsum[1][j] * (1.0f / Nn);
        float var = g_bnsq[1][j] * (1.0f / Nn) - mu * mu;
        float sc  = rsqrtf(var + 1e-5f) * gamma[j];
        ssc[j] = sc;
        ssh[j] = beta[j] - mu * sc;
    }
    __syncthreads();

    int r = blockIdx.x * 256 + threadIdx.x;
    if (r >= Nn) return;

    float al[10], ar[10];
    #pragma unroll
    for (int j = 0; j < 10; j++) { al[j] = 0.f; ar[j] = sb[j]; }

    const float4* h4 = (const float4*)(g_out + (size_t)r * 64);
    #pragma unroll 1
    for (int k4 = 0; k4 < 16; k4++) {
        float4 h = __ldg(h4 + k4);
        h.x = fmaxf(fmaf(h.x, ssc[k4 * 4 + 0], ssh[k4 * 4 + 0]), 0.f);
        h.y = fmaxf(fmaf(h.y, ssc[k4 * 4 + 1], ssh[k4 * 4 + 1]), 0.f);
        h.z = fmaxf(fmaf(h.z, ssc[k4 * 4 + 2], ssh[k4 * 4 + 2]), 0.f);
        h.w = fmaxf(fmaf(h.w, ssc[k4 * 4 + 3], ssh[k4 * 4 + 3]), 0.f);
        #pragma unroll
        for (int kk = 0; kk < 4; kk++) {
            float hv = kk == 0 ? h.x : kk == 1 ? h.y : kk == 2 ? h.z : h.w;
            int k = k4 * 4 + kk;
            #pragma unroll
            for (int j = 0; j < 10; j++) {
                al[j] += hv * sWl[k * 10 + j];
                ar[j] += hv * sWr[k * 10 + j];
            }
        }
    }
    __half2* z2 = (__half2*)(g_z16 + (size_t)r * 16);
    #pragma unroll
    for (int j2 = 0; j2 < 5; j2++)
        z2[j2] = __floats2half2_rn(al[j2 * 2], al[j2 * 2 + 1]);
    z2[5] = __floats2half2_rn(0.f, 0.f);
    z2[6] = __floats2half2_rn(0.f, 0.f);
    z2[7] = __floats2half2_rn(0.f, 0.f);
    #pragma unroll
    for (int j = 0; j < 10; j++) out[(size_t)r * 10 + j] = ar[j];
}

// ---------------- aggregate projected z rows (fp16, 16-wide) into out --------
__global__ void k_agg10(float* __restrict__ out) {
    int gt = blockIdx.x * blockDim.x + threadIdx.x;
    int w = gt >> 5, lane = gt & 31;
    if (w >= Nn) return;
    int beg = g_rowptr[w], end = g_rowptr[w + 1];
    int half = lane >> 4, col = lane & 15;
    float a = 0.f;
    for (int e = beg + half; e < end; e += 2) {
        int s = __ldg(&g_colidx[e]);
        a += __half2float(__ldg(g_z16 + (size_t)s * 16 + col));
    }
    a += __shfl_down_sync(0xffffffffu, a, 16);
    if (lane < 10) {
        float inv = 1.0f / (float)max(end - beg, 1);
        out[(size_t)w * 10 + lane] += a * inv;
    }
}

// ---------------- launch -----------------------------------------------------
extern "C" void kernel_launch(void* const* d_in, const int* in_sizes, int n_in,
                              void* d_out, int out_size) {
    const float* x   = (const float*)d_in[0];
    const void*  ei  = d_in[1];
    const float* Wl1 = (const float*)d_in[2];
    const float* Wr1 = (const float*)d_in[3];
    const float* b1  = (const float*)d_in[4];
    const float* g1  = (const float*)d_in[5];
    const float* be1 = (const float*)d_in[6];
    const float* Wl2 = (const float*)d_in[7];
    const float* Wr2 = (const float*)d_in[8];
    const float* b2  = (const float*)d_in[9];
    const float* g2  = (const float*)d_in[10];
    const float* be2 = (const float*)d_in[11];
    const float* Wl3 = (const float*)d_in[12];
    const float* Wr3 = (const float*)d_in[13];
    const float* b3  = (const float*)d_in[14];
    float* out = (float*)d_out;

    const int NBLK_N   = (Nn + 255) / 256;      // 391
    const int NBLK_G   = (Nn + 63) / 64;        // 1563 (fused agg+gemm)
    const int NBLK_AGG = (Nn * 32 + 255) / 256; // 12500 (k_agg10)
    const int NBLK_E   = 2048;
    const int NBLK_EW  = 592;

    // CSR build + fp16 x table (6 launches)
    k_init   <<<NBLK_EW, 256>>>(ei, x);
    k_hist   <<<NBLK_E, 256>>>(ei);
    k_scan1  <<<NSB, 512>>>();
    k_scan2b <<<1, 256>>>();
    k_scan3  <<<NBLK_N, 256>>>();
    k_scatter<<<NBLK_E, 256>>>(ei);

    // Layer 1: fused agg+GEMM(+BN stats), then BN apply -> h16
    k_aggemm <<<NBLK_G, 256>>>(0, Wl1, Wr1, b1);
    k_bnapply<<<NBLK_EW, 256>>>(0, g1, be1);

    // Layer 2: fused agg+GEMM(+BN stats)
    k_aggemm <<<NBLK_G, 256>>>(1, Wl2, Wr2, b2);

    // Layer 3: fused BN(1)+proj, then aggregate z
    k_bnproj <<<NBLK_N, 256>>>(g2, be2, Wl3, Wr3, b3, out);
    k_agg10  <<<NBLK_AGG, 256>>>(out);
}

// round 17
// speedup vs baseline: 1.0981x; 1.0981x over previous
#include <cuda_runtime.h>
#include <cuda_fp16.h>
#include <mma.h>
#include <math.h>

using namespace nvcuda;

#define Nn 100000
#define Ee 1600000
#define NSB 196   // ceil(Nn/512)
#define NPAD (Nn + 64)   // tables padded so tail WMMA tiles read zeroed .bss

typedef unsigned long long ull;

// ---------------- scratch (device globals) -----------------------------------
__device__ int   g_rowptr[Nn + 1];
__device__ int   g_cursor[Nn];
__device__ int   g_colidx[Ee];
__device__ int   g_bsum[NSB];
__device__ int   g_is64;
__device__ float g_out [(size_t)Nn * 64];
__device__ __align__(16) __half2 g_x16[(size_t)NPAD * 32];  // fp16 x rows
__device__ __align__(16) __half2 g_h16[(size_t)NPAD * 32];  // fp16 h rows
__device__ __align__(16) __half2 g_m16[(size_t)NPAD * 32];  // fp16 mean rows
__device__ __align__(16) __half  g_z16[(size_t)Nn * 16];    // layer-3 z rows (fp16)
__device__ float g_bnsum[2][64];
__device__ float g_bnsq [2][64];

__device__ __forceinline__ int edge_at(const void* ei, long long i, int is64) {
    return is64 ? (int)__ldg(&((const long long*)ei)[i]) : __ldg(&((const int*)ei)[i]);
}

// ---------------- init: cursor zero + BN zero + dtype detect + x->fp16 -------
__global__ void k_init(const void* ei, const float* __restrict__ x) {
    int i = blockIdx.x * blockDim.x + threadIdx.x;
    if (i < Nn) g_cursor[i] = 0;
    if (blockIdx.x == 0) {
        if (threadIdx.x < 64) {
            g_bnsum[0][threadIdx.x] = 0.f; g_bnsq[0][threadIdx.x] = 0.f;
            g_bnsum[1][threadIdx.x] = 0.f; g_bnsq[1][threadIdx.x] = 0.f;
        }
        if (threadIdx.x >= 64 && threadIdx.x < 96) {
            int lane = threadIdx.x - 64;
            const long long* q = (const long long*)ei;
            long long v = q[(long long)lane * 33331];
            unsigned bad = __ballot_sync(0xffffffffu, v < 0 || v >= Nn);
            if (lane == 0) g_is64 = (bad == 0) ? 1 : 0;
        }
    }
    long long stride = (long long)gridDim.x * blockDim.x;
    const float2* p = (const float2*)x;
    for (long long t = i; t < (long long)Nn * 32; t += stride)
        g_x16[t] = __float22half2_rn(__ldg(p + t));
}

// ---------------- CSR build --------------------------------------------------
__global__ void k_hist(const void* ei) {
    int is64 = g_is64;
    long long stride = (long long)gridDim.x * blockDim.x;
    for (long long e = blockIdx.x * (long long)blockDim.x + threadIdx.x; e < Ee; e += stride) {
        int d = edge_at(ei, Ee + e, is64);
        atomicAdd(&g_cursor[d], 1);
    }
}

__global__ void k_scan1() {
    __shared__ int sh[512];
    int i = blockIdx.x * 512 + threadIdx.x;
    int v = (i < Nn) ? g_cursor[i] : 0;
    sh[threadIdx.x] = v;
    __syncthreads();
    for (int off = 1; off < 512; off <<= 1) {
        int t = (threadIdx.x >= off) ? sh[threadIdx.x - off] : 0;
        __syncthreads();
        sh[threadIdx.x] += t;
        __syncthreads();
    }
    if (i < Nn) g_rowptr[i + 1] = sh[threadIdx.x];
    if (threadIdx.x == 511) g_bsum[blockIdx.x] = sh[511];
}

__global__ void k_scan2b() {
    __shared__ int sh[256];
    int tid = threadIdx.x;
    int v = (tid < NSB) ? g_bsum[tid] : 0;
    sh[tid] = v;
    __syncthreads();
    for (int off = 1; off < 256; off <<= 1) {
        int t = (tid >= off) ? sh[tid - off] : 0;
        __syncthreads();
        sh[tid] += t;
        __syncthreads();
    }
    if (tid < NSB) g_bsum[tid] = sh[tid] - v;   // exclusive
}

__global__ void k_scan3() {
    int i = blockIdx.x * blockDim.x + threadIdx.x;
    if (i < Nn) {
        int fin = g_rowptr[i + 1] + g_bsum[i >> 9];
        g_rowptr[i + 1] = fin;
        if (i + 1 < Nn) g_cursor[i + 1] = fin;
    }
    if (i == 0) { g_rowptr[0] = 0; g_cursor[0] = 0; }
}

__global__ void k_scatter(const void* ei) {
    int is64 = g_is64;
    long long stride = (long long)gridDim.x * blockDim.x;
    for (long long e = blockIdx.x * (long long)blockDim.x + threadIdx.x; e < Ee; e += stride) {
        int d = edge_at(ei, Ee + e, is64);
        int s = edge_at(ei, e,      is64);
        int pos = atomicAdd(&g_cursor[d], 1);
        g_colidx[pos] = s;
    }
}

// ---------------- HALF-WARP mean aggregation (fp16 gather) -> fp16 mean ------
// (R15-proven: part of the 360.6us champion)
__global__ void k_agg16h(int which) {
    const uint2* __restrict__ p = (const uint2*)(which ? g_h16 : g_x16);
    int gt = blockIdx.x * blockDim.x + threadIdx.x;
    int w = gt >> 4;
    if (w >= Nn) return;
    int l16 = threadIdx.x & 15;
    unsigned hm = 0xFFFFu << (threadIdx.x & 16);

    int beg = g_rowptr[w], end = g_rowptr[w + 1];
    float a0 = 0.f, a1 = 0.f, a2 = 0.f, a3 = 0.f;

    for (int e = beg; e < end; e += 16) {
        int cnt = min(16, end - e);
        int s = (l16 < cnt) ? __ldg(&g_colidx[e + l16]) : 0;
        int j = 0;
        for (; j + 2 <= cnt; j += 2) {
            int s0 = __shfl_sync(hm, s, j,     16);
            int s1 = __shfl_sync(hm, s, j + 1, 16);
            uint2 v0 = __ldg(p + (size_t)s0 * 16 + l16);
            uint2 v1 = __ldg(p + (size_t)s1 * 16 + l16);
            float2 f;
            f = __half22float2(*(__half2*)&v0.x); a0 += f.x; a1 += f.y;
            f = __half22float2(*(__half2*)&v0.y); a2 += f.x; a3 += f.y;
            f = __half22float2(*(__half2*)&v1.x); a0 += f.x; a1 += f.y;
            f = __half22float2(*(__half2*)&v1.y); a2 += f.x; a3 += f.y;
        }
        if (j < cnt) {
            int s0 = __shfl_sync(hm, s, j, 16);
            uint2 v0 = __ldg(p + (size_t)s0 * 16 + l16);
            float2 f;
            f = __half22float2(*(__half2*)&v0.x); a0 += f.x; a1 += f.y;
            f = __half22float2(*(__half2*)&v0.y); a2 += f.x; a3 += f.y;
        }
    }
    float inv = 1.0f / (float)max(end - beg, 1);
    __half2 o0 = __floats2half2_rn(a0 * inv, a1 * inv);
    __half2 o1 = __floats2half2_rn(a2 * inv, a3 * inv);
    uint2* o = (uint2*)(g_m16 + (size_t)w * 32 + l16 * 2);
    *o = make_uint2(*(unsigned*)&o0, *(unsigned*)&o1);
}

// ---------------- WMMA dual-GEMM + bias + L2 norm + FUSED BN-STATS -----------
// (R15-proven: part of the 360.6us champion)
__global__ void __launch_bounds__(256) k_gemmT(int which,
                                               const float* __restrict__ Wl,
                                               const float* __restrict__ Wr,
                                               const float* __restrict__ b) {
    __shared__ __align__(16) __half sWl[4096];
    __shared__ __align__(16) __half sWr[4096];
    __shared__ __align__(16) float sC[64 * 68];
    __shared__ float sb[64];
    __shared__ float sSum[64], sSq[64];

    const int T = threadIdx.x;
    const int row0 = blockIdx.x * 64;

    for (int i = T; i < 4096; i += 256) {
        sWl[i] = __float2half_rn(Wl[i]);
        sWr[i] = __float2half_rn(Wr[i]);
    }
    if (T < 64) { sb[T] = b[T]; sSum[T] = 0.f; sSq[T] = 0.f; }
    __syncthreads();

    const __half* __restrict__ own = (const __half*)(which ? g_h16 : g_x16);
    const __half* __restrict__ mn  = (const __half*)g_m16;

    int warp = T >> 5;
    #pragma unroll
    for (int t = warp; t < 16; t += 8) {
        int tr = t >> 2, tc = t & 3;
        wmma::fragment<wmma::accumulator, 16, 16, 16, float> acc;
        wmma::fill_fragment(acc, 0.0f);
        const __half* Ar = mn  + (size_t)(row0 + tr * 16) * 64;
        const __half* Hr = own + (size_t)(row0 + tr * 16) * 64;
        #pragma unroll
        for (int ks = 0; ks < 4; ks++) {
            wmma::fragment<wmma::matrix_a, 16, 16, 16, __half, wmma::row_major> a;
            wmma::fragment<wmma::matrix_b, 16, 16, 16, __half, wmma::col_major> w;
            wmma::load_matrix_sync(a, Ar + ks * 16, 64);
            wmma::load_matrix_sync(w, sWl + ks * 16 + tc * 16 * 64, 64);
            wmma::mma_sync(acc, a, w, acc);
            wmma::load_matrix_sync(a, Hr + ks * 16, 64);
            wmma::load_matrix_sync(w, sWr + ks * 16 + tc * 16 * 64, 64);
            wmma::mma_sync(acc, a, w, acc);
        }
        wmma::store_matrix_sync(sC + tr * 16 * 68 + tc * 16, acc, 68, wmma::mem_row_major);
    }
    __syncthreads();

    int row = T >> 2, seg = T & 3, lane = T & 31;
    const float* crow = sC + row * 68 + seg * 16;
    float v[16];
    float s = 0.f;
    #pragma unroll
    for (int i = 0; i < 16; i++) {
        float t = crow[i] + sb[seg * 16 + i];
        v[i] = t;
        s += t * t;
    }
    s += __shfl_xor_sync(0xffffffffu, s, 1);
    s += __shfl_xor_sync(0xffffffffu, s, 2);
    float sc = 1.0f / fmaxf(sqrtf(s), 1e-12f);
    int grow = row0 + row;
    bool live = (grow < Nn);
    if (live) {
        float4* o = (float4*)(g_out + (size_t)grow * 64 + seg * 16);
        #pragma unroll
        for (int j4 = 0; j4 < 4; j4++)
            o[j4] = make_float4(v[j4 * 4] * sc, v[j4 * 4 + 1] * sc,
                                v[j4 * 4 + 2] * sc, v[j4 * 4 + 3] * sc);
    }
    #pragma unroll
    for (int half = 0; half < 2; half++) {
        float sv[8], qv[8];
        #pragma unroll
        for (int i = 0; i < 8; i++) {
            float t = live ? v[half * 8 + i] * sc : 0.f;
            sv[i] = t; qv[i] = t * t;
        }
        #pragma unroll
        for (int off = 4; off <= 16; off <<= 1) {
            #pragma unroll
            for (int i = 0; i < 8; i++) {
                sv[i] += __shfl_xor_sync(0xffffffffu, sv[i], off);
                qv[i] += __shfl_xor_sync(0xffffffffu, qv[i], off);
            }
        }
        if ((lane >> 2) == 0) {
            #pragma unroll
            for (int i = 0; i < 8; i++) {
                int col = seg * 16 + half * 8 + i;
                atomicAdd(&sSum[col], sv[i]);
                atomicAdd(&sSq[col],  qv[i]);
            }
        }
    }
    __syncthreads();
    if (T < 64) {
        atomicAdd(&g_bnsum[which][T], sSum[T]);
        atomicAdd(&g_bnsq [which][T], sSq[T]);
    }
}

// ---------------- bn apply (+ReLU) -> fp16 g_h16 (layer-1 only) --------------
__global__ void k_bnapply(int slot, const float* __restrict__ gamma,
                          const float* __restrict__ beta) {
    __shared__ float ssc[64], ssh[64];
    if (threadIdx.x < 64) {
        int j = threadIdx.x;
        float mu  = g_bnsum[slot][j] * (1.0f / Nn);
        float var = g_bnsq[slot][j] * (1.0f / Nn) - mu * mu;
        float sc  = rsqrtf(var + 1e-5f) * gamma[j];
        ssc[j] = sc;
        ssh[j] = beta[j] - mu * sc;
    }
    __syncthreads();
    long long stride = (long long)gridDim.x * blockDim.x;
    const float2* p = (const float2*)g_out;
    for (long long i = blockIdx.x * (long long)blockDim.x + threadIdx.x;
         i < (long long)Nn * 32; i += stride) {
        int c2 = (int)(i & 31);
        float2 v = p[i];
        float y0 = fmaxf(v.x * ssc[c2 * 2]     + ssh[c2 * 2],     0.f);
        float y1 = fmaxf(v.y * ssc[c2 * 2 + 1] + ssh[c2 * 2 + 1], 0.f);
        g_h16[i] = __floats2half2_rn(y0, y1);
    }
}

// ---------------- FUSED BN(1)+ReLU + layer-3 projection (R16-proven) ---------
__global__ void __launch_bounds__(256) k_bnproj(const float* __restrict__ gamma,
                                                const float* __restrict__ beta,
                                                const float* __restrict__ Wl,
                                                const float* __restrict__ Wr,
                                                const float* __restrict__ b,
                                                float* __restrict__ out) {
    __shared__ float sWl[640];
    __shared__ float sWr[640];
    __shared__ float sb[10];
    __shared__ float ssc[64], ssh[64];
    for (int i = threadIdx.x; i < 640; i += 256) {
        int j = i / 64, k = i % 64;
        sWl[k * 10 + j] = Wl[i];
        sWr[k * 10 + j] = Wr[i];
    }
    if (threadIdx.x < 10) sb[threadIdx.x] = b[threadIdx.x];
    if (threadIdx.x >= 64 && threadIdx.x < 128) {
        int j = threadIdx.x - 64;
        float mu  = g_bnsum[1][j] * (1.0f / Nn);
        float var = g_bnsq[1][j] * (1.0f / Nn) - mu * mu;
        float sc  = rsqrtf(var + 1e-5f) * gamma[j];
        ssc[j] = sc;
        ssh[j] = beta[j] - mu * sc;
    }
    __syncthreads();

    int r = blockIdx.x * 256 + threadIdx.x;
    if (r >= Nn) return;

    float al[10], ar[10];
    #pragma unroll
    for (int j = 0; j < 10; j++) { al[j] = 0.f; ar[j] = sb[j]; }

    const float4* h4 = (const float4*)(g_out + (size_t)r * 64);
    #pragma unroll 1
    for (int k4 = 0; k4 < 16; k4++) {
        float4 h = __ldg(h4 + k4);
        h.x = fmaxf(fmaf(h.x, ssc[k4 * 4 + 0], ssh[k4 * 4 + 0]), 0.f);
        h.y = fmaxf(fmaf(h.y, ssc[k4 * 4 + 1], ssh[k4 * 4 + 1]), 0.f);
        h.z = fmaxf(fmaf(h.z, ssc[k4 * 4 + 2], ssh[k4 * 4 + 2]), 0.f);
        h.w = fmaxf(fmaf(h.w, ssc[k4 * 4 + 3], ssh[k4 * 4 + 3]), 0.f);
        #pragma unroll
        for (int kk = 0; kk < 4; kk++) {
            float hv = kk == 0 ? h.x : kk == 1 ? h.y : kk == 2 ? h.z : h.w;
            int k = k4 * 4 + kk;
            #pragma unroll
            for (int j = 0; j < 10; j++) {
                al[j] += hv * sWl[k * 10 + j];
                ar[j] += hv * sWr[k * 10 + j];
            }
        }
    }
    __half2* z2 = (__half2*)(g_z16 + (size_t)r * 16);
    #pragma unroll
    for (int j2 = 0; j2 < 5; j2++)
        z2[j2] = __floats2half2_rn(al[j2 * 2], al[j2 * 2 + 1]);
    z2[5] = __floats2half2_rn(0.f, 0.f);
    z2[6] = __floats2half2_rn(0.f, 0.f);
    z2[7] = __floats2half2_rn(0.f, 0.f);
    #pragma unroll
    for (int j = 0; j < 10; j++) out[(size_t)r * 10 + j] = ar[j];
}

// ---------------- aggregate projected z rows (fp16, 16-wide) into out --------
__global__ void k_agg10(float* __restrict__ out) {
    int gt = blockIdx.x * blockDim.x + threadIdx.x;
    int w = gt >> 5, lane = gt & 31;
    if (w >= Nn) return;
    int beg = g_rowptr[w], end = g_rowptr[w + 1];
    int half = lane >> 4, col = lane & 15;
    float a = 0.f;
    for (int e = beg + half; e < end; e += 2) {
        int s = __ldg(&g_colidx[e]);
        a += __half2float(__ldg(g_z16 + (size_t)s * 16 + col));
    }
    a += __shfl_down_sync(0xffffffffu, a, 16);
    if (lane < 10) {
        float inv = 1.0f / (float)max(end - beg, 1);
        out[(size_t)w * 10 + lane] += a * inv;
    }
}

// ---------------- launch -----------------------------------------------------
extern "C" void kernel_launch(void* const* d_in, const int* in_sizes, int n_in,
                              void* d_out, int out_size) {
    const float* x   = (const float*)d_in[0];
    const void*  ei  = d_in[1];
    const float* Wl1 = (const float*)d_in[2];
    const float* Wr1 = (const float*)d_in[3];
    const float* b1  = (const float*)d_in[4];
    const float* g1  = (const float*)d_in[5];
    const float* be1 = (const float*)d_in[6];
    const float* Wl2 = (const float*)d_in[7];
    const float* Wr2 = (const float*)d_in[8];
    const float* b2  = (const float*)d_in[9];
    const float* g2  = (const float*)d_in[10];
    const float* be2 = (const float*)d_in[11];
    const float* Wl3 = (const float*)d_in[12];
    const float* Wr3 = (const float*)d_in[13];
    const float* b3  = (const float*)d_in[14];
    float* out = (float*)d_out;

    const int NBLK_N    = (Nn + 255) / 256;      // 391
    const int NBLK_G    = (Nn + 63) / 64;        // 1563 (wmma gemm)
    const int NBLK_AGGH = (Nn * 16 + 255) / 256; // 6250 (half-warp agg)
    const int NBLK_AGG  = (Nn * 32 + 255) / 256; // 12500 (k_agg10)
    const int NBLK_E    = 2048;
    const int NBLK_EW   = 592;

    // CSR build + fp16 x table (6 launches)
    k_init   <<<NBLK_EW, 256>>>(ei, x);
    k_hist   <<<NBLK_E, 256>>>(ei);
    k_scan1  <<<NSB, 512>>>();
    k_scan2b <<<1, 256>>>();
    k_scan3  <<<NBLK_N, 256>>>();
    k_scatter<<<NBLK_E, 256>>>(ei);

    // Layer 1: agg -> GEMM(+BN stats) -> BN apply -> h16
    k_agg16h <<<NBLK_AGGH, 256>>>(0);
    k_gemmT  <<<NBLK_G, 256>>>(0, Wl1, Wr1, b1);
    k_bnapply<<<NBLK_EW, 256>>>(0, g1, be1);

    // Layer 2: agg -> GEMM(+BN stats)
    k_agg16h <<<NBLK_AGGH, 256>>>(1);
    k_gemmT  <<<NBLK_G, 256>>>(1, Wl2, Wr2, b2);

    // Layer 3: fused BN(1)+proj -> aggregate z
    k_bnproj <<<NBLK_N, 256>>>(g2, be2, Wl3, Wr3, b3, out);
    k_agg10  <<<NBLK_AGG, 256>>>(out);
}